// round 1
// baseline (speedup 1.0000x reference)
#include <cuda_runtime.h>
#include <math.h>

#define BB 4
#define TT 2048
#define EE 256
#define HH 8
#define DD 32
#define JOINED 25

// Scratch (allocation-free rule: __device__ globals)
__device__ float g_q[BB*HH*TT*DD];
__device__ float g_k[BB*HH*TT*DD];
__device__ float g_v[BB*HH*TT*DD];
__device__ float g_ctx[BB*TT*EE];

// ---------------------------------------------------------------------------
// GEMM: y[m][n] = sum_k x[m][k] * W[n][k] + bias[n]
// Tile 64x64, K-step 16, 256 threads, 4x4 per thread.
// ---------------------------------------------------------------------------
#define GM 64
#define GN 64
#define GK 16

__global__ void __launch_bounds__(256) qkv_kernel(
    const float* __restrict__ x,
    const float* __restrict__ W0, const float* __restrict__ b0,
    const float* __restrict__ W1, const float* __restrict__ b1,
    const float* __restrict__ W2, const float* __restrict__ b2)
{
    const float* W; const float* bias; float* out;
    int z = blockIdx.z;
    if (z == 0)      { W = W0; bias = b0; out = g_q; }
    else if (z == 1) { W = W1; bias = b1; out = g_k; }
    else             { W = W2; bias = b2; out = g_v; }

    __shared__ float As[GM][GK + 1];
    __shared__ float Bs[GN][GK + 1];

    int tid = threadIdx.x;
    int tx = tid & 15, ty = tid >> 4;
    int m0 = blockIdx.x * GM;     // M = B*T = 8192
    int n0 = blockIdx.y * GN;     // N = 256

    float acc[4][4] = {};

    int lr = tid >> 2;            // 0..63
    int lc = (tid & 3) * 4;       // 0,4,8,12

    for (int k0 = 0; k0 < EE; k0 += GK) {
        float4 a4 = *(const float4*)(x + (m0 + lr) * EE + k0 + lc);
        As[lr][lc+0] = a4.x; As[lr][lc+1] = a4.y; As[lr][lc+2] = a4.z; As[lr][lc+3] = a4.w;
        float4 b4 = *(const float4*)(W + (n0 + lr) * EE + k0 + lc);
        Bs[lr][lc+0] = b4.x; Bs[lr][lc+1] = b4.y; Bs[lr][lc+2] = b4.z; Bs[lr][lc+3] = b4.w;
        __syncthreads();
        #pragma unroll
        for (int kk = 0; kk < GK; kk++) {
            float av[4], bv[4];
            #pragma unroll
            for (int i = 0; i < 4; i++) av[i] = As[ty*4 + i][kk];
            #pragma unroll
            for (int j = 0; j < 4; j++) bv[j] = Bs[tx*4 + j][kk];
            #pragma unroll
            for (int i = 0; i < 4; i++)
                #pragma unroll
                for (int j = 0; j < 4; j++)
                    acc[i][j] += av[i] * bv[j];
        }
        __syncthreads();
    }

    // scatter-store into [B,H,T,D]
    #pragma unroll
    for (int i = 0; i < 4; i++) {
        int m = m0 + ty*4 + i;
        int b = m / TT, t = m % TT;
        #pragma unroll
        for (int j = 0; j < 4; j++) {
            int n = n0 + tx*4 + j;
            int h = n >> 5, d = n & 31;
            out[((b*HH + h) * TT + t) * DD + d] = acc[i][j] + bias[n];
        }
    }
}

__global__ void __launch_bounds__(256) proj_kernel(
    const float* __restrict__ Wo, const float* __restrict__ bo,
    float* __restrict__ out)
{
    __shared__ float As[GM][GK + 1];
    __shared__ float Bs[GN][GK + 1];

    int tid = threadIdx.x;
    int tx = tid & 15, ty = tid >> 4;
    int m0 = blockIdx.x * GM;
    int n0 = blockIdx.y * GN;

    float acc[4][4] = {};
    int lr = tid >> 2;
    int lc = (tid & 3) * 4;

    for (int k0 = 0; k0 < EE; k0 += GK) {
        float4 a4 = *(const float4*)(g_ctx + (m0 + lr) * EE + k0 + lc);
        As[lr][lc+0] = a4.x; As[lr][lc+1] = a4.y; As[lr][lc+2] = a4.z; As[lr][lc+3] = a4.w;
        float4 b4 = *(const float4*)(Wo + (n0 + lr) * EE + k0 + lc);
        Bs[lr][lc+0] = b4.x; Bs[lr][lc+1] = b4.y; Bs[lr][lc+2] = b4.z; Bs[lr][lc+3] = b4.w;
        __syncthreads();
        #pragma unroll
        for (int kk = 0; kk < GK; kk++) {
            float av[4], bv[4];
            #pragma unroll
            for (int i = 0; i < 4; i++) av[i] = As[ty*4 + i][kk];
            #pragma unroll
            for (int j = 0; j < 4; j++) bv[j] = Bs[tx*4 + j][kk];
            #pragma unroll
            for (int i = 0; i < 4; i++)
                #pragma unroll
                for (int j = 0; j < 4; j++)
                    acc[i][j] += av[i] * bv[j];
        }
        __syncthreads();
    }

    #pragma unroll
    for (int i = 0; i < 4; i++) {
        int m = m0 + ty*4 + i;
        #pragma unroll
        for (int j = 0; j < 4; j++) {
            int n = n0 + tx*4 + j;
            out[m * EE + n] = acc[i][j] + bo[n];
        }
    }
}

// ---------------------------------------------------------------------------
// Flash-attention: 1 thread = 1 query row. Block = 128 queries.
// K/V tiles (32 keys x 32 dims) staged in smem; all inner-loop smem reads are
// warp broadcasts. Online softmax with register-resident 32-score tile.
// ---------------------------------------------------------------------------
#define AM 128
#define AN 32

__global__ void __launch_bounds__(128) attn_kernel()
{
    int tid = threadIdx.x;
    int h = blockIdx.y, b = blockIdx.z;
    int t = blockIdx.x * AM + tid;

    const float* Q = g_q + (size_t)((b*HH + h) * TT) * DD;
    const float* K = g_k + (size_t)((b*HH + h) * TT) * DD;
    const float* V = g_v + (size_t)((b*HH + h) * TT) * DD;

    __shared__ float Ks[AN][DD];
    __shared__ float Vs[AN][DD];

    float q[DD];
    #pragma unroll
    for (int i = 0; i < DD/4; i++) {
        float4 v4 = *(const float4*)(Q + (size_t)t * DD + i*4);
        q[i*4+0] = v4.x; q[i*4+1] = v4.y; q[i*4+2] = v4.z; q[i*4+3] = v4.w;
    }

    float acc[DD];
    #pragma unroll
    for (int d = 0; d < DD; d++) acc[d] = 0.f;
    float mrun = -1e30f, lrun = 0.f;
    const float scale = 0.17677669529663687f;   // 1/sqrt(32)

    int tmax = blockIdx.x * AM + AM - 1;        // last query in this block
    int ntiles = tmax / AN + 1;

    // loader indices: 128 threads x 8 floats = 1024 = 32x32
    int lrow = tid >> 2;            // 0..31
    int lcol = (tid & 3) * 8;       // 0,8,16,24

    for (int tile = 0; tile < ntiles; tile++) {
        int tile0 = tile * AN;
        __syncthreads();
        *(float4*)&Ks[lrow][lcol]     = *(const float4*)(K + (size_t)(tile0 + lrow) * DD + lcol);
        *(float4*)&Ks[lrow][lcol + 4] = *(const float4*)(K + (size_t)(tile0 + lrow) * DD + lcol + 4);
        *(float4*)&Vs[lrow][lcol]     = *(const float4*)(V + (size_t)(tile0 + lrow) * DD + lcol);
        *(float4*)&Vs[lrow][lcol + 4] = *(const float4*)(V + (size_t)(tile0 + lrow) * DD + lcol + 4);
        __syncthreads();

        if (tile0 > t) continue;    // fully-future tile for this query

        float sc[AN];
        int r = tile0 % JOINED;
        #pragma unroll
        for (int j = 0; j < AN; j++) {
            float s = 0.f;
            #pragma unroll
            for (int kk = 0; kk < DD; kk++) s += q[kk] * Ks[j][kk];
            int sidx = tile0 + j;
            bool valid = (sidx <= t) && (r != JOINED - 1);
            sc[j] = valid ? s * scale : -1e30f;
            r = (r == JOINED - 1) ? 0 : r + 1;
        }

        float tmx = -1e30f;
        #pragma unroll
        for (int j = 0; j < AN; j++) tmx = fmaxf(tmx, sc[j]);
        float mnew = fmaxf(mrun, tmx);
        float corr = __expf(mrun - mnew);
        lrun *= corr;
        #pragma unroll
        for (int d = 0; d < DD; d++) acc[d] *= corr;

        #pragma unroll
        for (int j = 0; j < AN; j++) {
            float p = __expf(sc[j] - mnew);
            lrun += p;
            #pragma unroll
            for (int d = 0; d < DD; d++) acc[d] += p * Vs[j][d];
        }
        mrun = mnew;
    }

    float inv = 1.f / lrun;
    float* o = g_ctx + (size_t)(b * TT + t) * EE + h * DD;
    #pragma unroll
    for (int i = 0; i < DD/4; i++) {
        float4 v4;
        v4.x = acc[i*4+0]*inv; v4.y = acc[i*4+1]*inv;
        v4.z = acc[i*4+2]*inv; v4.w = acc[i*4+3]*inv;
        *(float4*)(o + i*4) = v4;
    }
}

// ---------------------------------------------------------------------------
extern "C" void kernel_launch(void* const* d_in, const int* in_sizes, int n_in,
                              void* d_out, int out_size)
{
    const float* x  = (const float*)d_in[0];
    const float* Wq = (const float*)d_in[1];
    const float* bq = (const float*)d_in[2];
    const float* Wk = (const float*)d_in[3];
    const float* bk = (const float*)d_in[4];
    const float* Wv = (const float*)d_in[5];
    const float* bv = (const float*)d_in[6];
    const float* Wo = (const float*)d_in[7];
    const float* bo = (const float*)d_in[8];
    float* out = (float*)d_out;

    dim3 gqkv((BB*TT)/GM, EE/GN, 3);
    qkv_kernel<<<gqkv, 256>>>(x, Wq, bq, Wk, bk, Wv, bv);

    dim3 gattn(TT/AM, HH, BB);
    attn_kernel<<<gattn, AM>>>();

    dim3 gproj((BB*TT)/GM, EE/GN, 1);
    proj_kernel<<<gproj, 256>>>(Wo, bo, out);
}

// round 5
// speedup vs baseline: 1.9216x; 1.9216x over previous
#include <cuda_runtime.h>
#include <math.h>

#define BB 4
#define TT 2048
#define EE 256
#define HH 8
#define DD 32
#define JOINED 25

// Scratch (allocation-free rule: __device__ globals)
__device__ float g_q[BB*HH*TT*DD];
__device__ float g_k[BB*HH*TT*DD];
__device__ float g_v[BB*HH*TT*DD];
__device__ float g_ctx[BB*TT*EE];

// ---------------------------------------------------------------------------
// GEMM: y[m][n] = sum_k x[m][k] * W[n][k] + bias[n]
// ---------------------------------------------------------------------------
#define GM 64
#define GN 64
#define GK 16

__global__ void __launch_bounds__(256) qkv_kernel(
    const float* __restrict__ x,
    const float* __restrict__ W0, const float* __restrict__ b0,
    const float* __restrict__ W1, const float* __restrict__ b1,
    const float* __restrict__ W2, const float* __restrict__ b2)
{
    const float* W; const float* bias; float* out;
    int z = blockIdx.z;
    if (z == 0)      { W = W0; bias = b0; out = g_q; }
    else if (z == 1) { W = W1; bias = b1; out = g_k; }
    else             { W = W2; bias = b2; out = g_v; }

    __shared__ float As[GM][GK + 1];
    __shared__ float Bs[GN][GK + 1];

    int tid = threadIdx.x;
    int tx = tid & 15, ty = tid >> 4;
    int m0 = blockIdx.x * GM;
    int n0 = blockIdx.y * GN;

    float acc[4][4] = {};
    int lr = tid >> 2;
    int lc = (tid & 3) * 4;

    for (int k0 = 0; k0 < EE; k0 += GK) {
        float4 a4 = *(const float4*)(x + (m0 + lr) * EE + k0 + lc);
        As[lr][lc+0] = a4.x; As[lr][lc+1] = a4.y; As[lr][lc+2] = a4.z; As[lr][lc+3] = a4.w;
        float4 b4 = *(const float4*)(W + (n0 + lr) * EE + k0 + lc);
        Bs[lr][lc+0] = b4.x; Bs[lr][lc+1] = b4.y; Bs[lr][lc+2] = b4.z; Bs[lr][lc+3] = b4.w;
        __syncthreads();
        #pragma unroll
        for (int kk = 0; kk < GK; kk++) {
            float av[4], bv[4];
            #pragma unroll
            for (int i = 0; i < 4; i++) av[i] = As[ty*4 + i][kk];
            #pragma unroll
            for (int j = 0; j < 4; j++) bv[j] = Bs[tx*4 + j][kk];
            #pragma unroll
            for (int i = 0; i < 4; i++)
                #pragma unroll
                for (int j = 0; j < 4; j++)
                    acc[i][j] += av[i] * bv[j];
        }
        __syncthreads();
    }

    #pragma unroll
    for (int i = 0; i < 4; i++) {
        int m = m0 + ty*4 + i;
        int b = m / TT, t = m % TT;
        #pragma unroll
        for (int j = 0; j < 4; j++) {
            int n = n0 + tx*4 + j;
            int h = n >> 5, d = n & 31;
            out[((b*HH + h) * TT + t) * DD + d] = acc[i][j] + bias[n];
        }
    }
}

__global__ void __launch_bounds__(256) proj_kernel(
    const float* __restrict__ Wo, const float* __restrict__ bo,
    float* __restrict__ out)
{
    __shared__ float As[GM][GK + 1];
    __shared__ float Bs[GN][GK + 1];

    int tid = threadIdx.x;
    int tx = tid & 15, ty = tid >> 4;
    int m0 = blockIdx.x * GM;
    int n0 = blockIdx.y * GN;

    float acc[4][4] = {};
    int lr = tid >> 2;
    int lc = (tid & 3) * 4;

    for (int k0 = 0; k0 < EE; k0 += GK) {
        float4 a4 = *(const float4*)(g_ctx + (m0 + lr) * EE + k0 + lc);
        As[lr][lc+0] = a4.x; As[lr][lc+1] = a4.y; As[lr][lc+2] = a4.z; As[lr][lc+3] = a4.w;
        float4 b4 = *(const float4*)(Wo + (n0 + lr) * EE + k0 + lc);
        Bs[lr][lc+0] = b4.x; Bs[lr][lc+1] = b4.y; Bs[lr][lc+2] = b4.z; Bs[lr][lc+3] = b4.w;
        __syncthreads();
        #pragma unroll
        for (int kk = 0; kk < GK; kk++) {
            float av[4], bv[4];
            #pragma unroll
            for (int i = 0; i < 4; i++) av[i] = As[ty*4 + i][kk];
            #pragma unroll
            for (int j = 0; j < 4; j++) bv[j] = Bs[tx*4 + j][kk];
            #pragma unroll
            for (int i = 0; i < 4; i++)
                #pragma unroll
                for (int j = 0; j < 4; j++)
                    acc[i][j] += av[i] * bv[j];
        }
        __syncthreads();
    }

    #pragma unroll
    for (int i = 0; i < 4; i++) {
        int m = m0 + ty*4 + i;
        #pragma unroll
        for (int j = 0; j < 4; j++) {
            int n = n0 + tx*4 + j;
            out[m * EE + n] = acc[i][j] + bo[n];
        }
    }
}

// ---------------------------------------------------------------------------
// Flash attention with mma.sync m16n8k8 tf32.
// Block = 4 warps, 64 queries (warp w owns rows qw..qw+15). 64-key tiles.
// ---------------------------------------------------------------------------
__device__ __forceinline__ unsigned cvt_tf32(float f) {
    unsigned r;
    asm("cvt.rna.tf32.f32 %0, %1;" : "=r"(r) : "f"(f));
    return r;
}

__device__ __forceinline__ void mma_tf32(
    float& c0, float& c1, float& c2, float& c3,
    unsigned a0, unsigned a1, unsigned a2, unsigned a3,
    unsigned b0, unsigned b1)
{
    asm volatile(
        "mma.sync.aligned.m16n8k8.row.col.f32.tf32.tf32.f32 "
        "{%0,%1,%2,%3}, {%4,%5,%6,%7}, {%8,%9}, {%0,%1,%2,%3};\n"
        : "+f"(c0), "+f"(c1), "+f"(c2), "+f"(c3)
        : "r"(a0), "r"(a1), "r"(a2), "r"(a3), "r"(b0), "r"(b1));
}

#define KSTRIDE 36
#define PSTRIDE 68

__global__ void __launch_bounds__(128) attn_kernel()
{
    __shared__ float Ks[64][KSTRIDE];
    __shared__ float Vs[64][KSTRIDE];
    __shared__ float Pb[4][16][PSTRIDE];

    int tid  = threadIdx.x;
    int w    = tid >> 5;
    int lane = tid & 31;
    int g    = lane >> 2;      // group id (row within m16 half)
    int t    = lane & 3;       // thread in group

    int h = blockIdx.y, b = blockIdx.z;
    int q0 = blockIdx.x * 64;
    int qw = q0 + w * 16;
    int r0 = qw + g;
    int r1 = qw + g + 8;

    const float* Q = g_q + (size_t)((b*HH + h)) * TT * DD;
    const float* K = g_k + (size_t)((b*HH + h)) * TT * DD;
    const float* V = g_v + (size_t)((b*HH + h)) * TT * DD;

    // preload Q fragments (scaled, tf32-rounded)
    const float scale = 0.17677669529663687f;  // 1/sqrt(32)
    unsigned qa[4][4];
    #pragma unroll
    for (int kk = 0; kk < 4; kk++) {
        qa[kk][0] = cvt_tf32(Q[(size_t)r0 * DD + kk*8 + t]     * scale);
        qa[kk][1] = cvt_tf32(Q[(size_t)r1 * DD + kk*8 + t]     * scale);
        qa[kk][2] = cvt_tf32(Q[(size_t)r0 * DD + kk*8 + t + 4] * scale);
        qa[kk][3] = cvt_tf32(Q[(size_t)r1 * DD + kk*8 + t + 4] * scale);
    }

    float o[4][4] = {};
    float m0 = -1e30f, m1 = -1e30f, l0 = 0.f, l1 = 0.f;

    int ntiles = blockIdx.x + 1;   // tiles 0 .. q0/64

    // loader mapping: 128 threads -> 64 rows x 2 halves of 16 floats
    int lrow = tid >> 1;
    int lcb  = (tid & 1) * 16;

    for (int tile = 0; tile < ntiles; tile++) {
        int j0 = tile * 64;
        __syncthreads();
        {
            const float* kp = K + (size_t)(j0 + lrow) * DD + lcb;
            const float* vp = V + (size_t)(j0 + lrow) * DD + lcb;
            #pragma unroll
            for (int i = 0; i < 4; i++) {
                float4 kv = *(const float4*)(kp + i*4);
                float4 vv = *(const float4*)(vp + i*4);
                float4 ko, vo;
                ko.x = __uint_as_float(cvt_tf32(kv.x));
                ko.y = __uint_as_float(cvt_tf32(kv.y));
                ko.z = __uint_as_float(cvt_tf32(kv.z));
                ko.w = __uint_as_float(cvt_tf32(kv.w));
                vo.x = __uint_as_float(cvt_tf32(vv.x));
                vo.y = __uint_as_float(cvt_tf32(vv.y));
                vo.z = __uint_as_float(cvt_tf32(vv.z));
                vo.w = __uint_as_float(cvt_tf32(vv.w));
                *(float4*)&Ks[lrow][lcb + i*4] = ko;
                *(float4*)&Vs[lrow][lcb + i*4] = vo;
            }
        }
        __syncthreads();

        if (j0 > qw + 15) continue;   // entire tile is future for this warp

        // S = Q K^T  (16 x 64) in 8 n-tiles
        float sc[8][4];
        #pragma unroll
        for (int nt = 0; nt < 8; nt++) {
            float c0 = 0.f, c1 = 0.f, c2 = 0.f, c3 = 0.f;
            #pragma unroll
            for (int kk = 0; kk < 4; kk++) {
                unsigned b0 = __float_as_uint(Ks[nt*8 + g][kk*8 + t]);
                unsigned b1 = __float_as_uint(Ks[nt*8 + g][kk*8 + t + 4]);
                mma_tf32(c0, c1, c2, c3,
                         qa[kk][0], qa[kk][1], qa[kk][2], qa[kk][3], b0, b1);
            }
            sc[nt][0] = c0; sc[nt][1] = c1; sc[nt][2] = c2; sc[nt][3] = c3;
        }

        // mask: causal + (col % 25 == 24) zeroed columns
        #pragma unroll
        for (int nt = 0; nt < 8; nt++) {
            int cA = j0 + nt*8 + 2*t;
            int cB = cA + 1;
            bool okA = (cA % JOINED) != (JOINED - 1);
            bool okB = (cB % JOINED) != (JOINED - 1);
            if (!(okA && cA <= r0)) sc[nt][0] = -1e30f;
            if (!(okB && cB <= r0)) sc[nt][1] = -1e30f;
            if (!(okA && cA <= r1)) sc[nt][2] = -1e30f;
            if (!(okB && cB <= r1)) sc[nt][3] = -1e30f;
        }

        // row max (per-lane then across quad)
        float mx0 = -1e30f, mx1 = -1e30f;
        #pragma unroll
        for (int nt = 0; nt < 8; nt++) {
            mx0 = fmaxf(mx0, fmaxf(sc[nt][0], sc[nt][1]));
            mx1 = fmaxf(mx1, fmaxf(sc[nt][2], sc[nt][3]));
        }
        mx0 = fmaxf(mx0, __shfl_xor_sync(0xffffffffu, mx0, 1));
        mx0 = fmaxf(mx0, __shfl_xor_sync(0xffffffffu, mx0, 2));
        mx1 = fmaxf(mx1, __shfl_xor_sync(0xffffffffu, mx1, 1));
        mx1 = fmaxf(mx1, __shfl_xor_sync(0xffffffffu, mx1, 2));

        float mn0 = fmaxf(m0, mx0), mn1 = fmaxf(m1, mx1);
        float cr0 = __expf(m0 - mn0), cr1 = __expf(m1 - mn1);
        m0 = mn0; m1 = mn1;

        __syncwarp();   // protect Pb against previous iteration's readers

        float ls0 = 0.f, ls1 = 0.f;
        #pragma unroll
        for (int nt = 0; nt < 8; nt++) {
            float p0 = __expf(sc[nt][0] - mn0);
            float p1 = __expf(sc[nt][1] - mn0);
            float p2 = __expf(sc[nt][2] - mn1);
            float p3 = __expf(sc[nt][3] - mn1);
            ls0 += p0 + p1;
            ls1 += p2 + p3;
            Pb[w][g    ][nt*8 + 2*t    ] = __uint_as_float(cvt_tf32(p0));
            Pb[w][g    ][nt*8 + 2*t + 1] = __uint_as_float(cvt_tf32(p1));
            Pb[w][g + 8][nt*8 + 2*t    ] = __uint_as_float(cvt_tf32(p2));
            Pb[w][g + 8][nt*8 + 2*t + 1] = __uint_as_float(cvt_tf32(p3));
        }
        ls0 += __shfl_xor_sync(0xffffffffu, ls0, 1);
        ls0 += __shfl_xor_sync(0xffffffffu, ls0, 2);
        ls1 += __shfl_xor_sync(0xffffffffu, ls1, 1);
        ls1 += __shfl_xor_sync(0xffffffffu, ls1, 2);
        l0 = l0 * cr0 + ls0;
        l1 = l1 * cr1 + ls1;

        #pragma unroll
        for (int dn = 0; dn < 4; dn++) {
            o[dn][0] *= cr0; o[dn][1] *= cr0;
            o[dn][2] *= cr1; o[dn][3] *= cr1;
        }

        __syncwarp();

        // O += P V   (16 x 32), K-dim = 64 keys
        #pragma unroll
        for (int kk = 0; kk < 8; kk++) {
            unsigned pa0 = __float_as_uint(Pb[w][g    ][kk*8 + t    ]);
            unsigned pa1 = __float_as_uint(Pb[w][g + 8][kk*8 + t    ]);
            unsigned pa2 = __float_as_uint(Pb[w][g    ][kk*8 + t + 4]);
            unsigned pa3 = __float_as_uint(Pb[w][g + 8][kk*8 + t + 4]);
            #pragma unroll
            for (int dn = 0; dn < 4; dn++) {
                unsigned b0 = __float_as_uint(Vs[kk*8 + t    ][dn*8 + g]);
                unsigned b1 = __float_as_uint(Vs[kk*8 + t + 4][dn*8 + g]);
                mma_tf32(o[dn][0], o[dn][1], o[dn][2], o[dn][3],
                         pa0, pa1, pa2, pa3, b0, b1);
            }
        }
    }

    float il0 = 1.f / l0, il1 = 1.f / l1;
    float* op0 = g_ctx + (size_t)(b*TT + r0) * EE + h*DD;
    float* op1 = g_ctx + (size_t)(b*TT + r1) * EE + h*DD;
    #pragma unroll
    for (int dn = 0; dn < 4; dn++) {
        float2 v0; v0.x = o[dn][0] * il0; v0.y = o[dn][1] * il0;
        float2 v1; v1.x = o[dn][2] * il1; v1.y = o[dn][3] * il1;
        *(float2*)(op0 + dn*8 + 2*t) = v0;
        *(float2*)(op1 + dn*8 + 2*t) = v1;
    }
}

// ---------------------------------------------------------------------------
extern "C" void kernel_launch(void* const* d_in, const int* in_sizes, int n_in,
                              void* d_out, int out_size)
{
    const float* x  = (const float*)d_in[0];
    const float* Wq = (const float*)d_in[1];
    const float* bq = (const float*)d_in[2];
    const float* Wk = (const float*)d_in[3];
    const float* bk = (const float*)d_in[4];
    const float* Wv = (const float*)d_in[5];
    const float* bv = (const float*)d_in[6];
    const float* Wo = (const float*)d_in[7];
    const float* bo = (const float*)d_in[8];
    float* out = (float*)d_out;

    dim3 gqkv((BB*TT)/GM, EE/GN, 3);
    qkv_kernel<<<gqkv, 256>>>(x, Wq, bq, Wk, bk, Wv, bv);

    dim3 gattn(TT/64, HH, BB);
    attn_kernel<<<gattn, 128>>>();

    dim3 gproj((BB*TT)/GM, EE/GN, 1);
    proj_kernel<<<gproj, 256>>>(Wo, bo, out);
}

// round 7
// speedup vs baseline: 2.7649x; 1.4388x over previous
#include <cuda_runtime.h>
#include <math.h>

#define BB 4
#define TT 2048
#define EE 256
#define HH 8
#define DD 32
#define JOINED 25

// Scratch (allocation-free rule: __device__ globals)
__device__ float g_q[BB*HH*TT*DD];
__device__ float g_k[BB*HH*TT*DD];
__device__ float g_v[BB*HH*TT*DD];
__device__ float g_ctx[BB*TT*EE];

__device__ __forceinline__ unsigned cvt_tf32(float f) {
    unsigned r;
    asm("cvt.rna.tf32.f32 %0, %1;" : "=r"(r) : "f"(f));
    return r;
}

__device__ __forceinline__ void mma_tf32(
    float& c0, float& c1, float& c2, float& c3,
    unsigned a0, unsigned a1, unsigned a2, unsigned a3,
    unsigned b0, unsigned b1)
{
    asm volatile(
        "mma.sync.aligned.m16n8k8.row.col.f32.tf32.tf32.f32 "
        "{%0,%1,%2,%3}, {%4,%5,%6,%7}, {%8,%9}, {%0,%1,%2,%3};\n"
        : "+f"(c0), "+f"(c1), "+f"(c2), "+f"(c3)
        : "r"(a0), "r"(a1), "r"(a2), "r"(a3), "r"(b0), "r"(b1));
}

// ---------------------------------------------------------------------------
// Epilogue functors (no device lambdas: harness compiles w/o --extended-lambda)
// ---------------------------------------------------------------------------
struct QKVEpilogue {
    float* out;            // g_q / g_k / g_v, layout [B,H,T,D]
    const float* bias;
    int b, tb, m0;
    __device__ __forceinline__ void operator()(int r, int n, float v0, float v1) const {
        int trow = tb + (r - m0);
        int h = n >> 5, d = n & 31;
        float2 o;
        o.x = v0 + bias[n];
        o.y = v1 + bias[n + 1];
        *(float2*)(out + ((size_t)((b*HH + h) * TT + trow)) * DD + d) = o;
    }
};

struct ProjEpilogue {
    float* out;            // [B*T, E]
    const float* bias;
    __device__ __forceinline__ void operator()(int r, int n, float v0, float v1) const {
        float2 o;
        o.x = v0 + bias[n];
        o.y = v1 + bias[n + 1];
        *(float2*)(out + (size_t)r * EE + n) = o;
    }
};

// ---------------------------------------------------------------------------
// TF32 tensor-core GEMM: y[m][n] = sum_k A[m][k] * W[n][k] (+ bias in epi)
// Block tile 128x64, K-step 16. 8 warps = 4(m) x 2(n), warp tile 32x32.
// smem row stride 20 -> g*20 mod 32 = {0,20,8,28,16,4,24,12}: 4-spaced,
// so fragment gathers (g,t) and (g,t+4) are bank-conflict-free.
// ---------------------------------------------------------------------------
#define TM 128
#define TN 64
#define TK 16
#define GS 20

template <typename EpiF>
__device__ __forceinline__ void gemm_tf32_body(
    const float* __restrict__ A, const float* __restrict__ W,
    int m0, int n0, EpiF epi)
{
    __shared__ float As[TM][GS];
    __shared__ float Bs[TN][GS];

    int tid  = threadIdx.x;
    int w    = tid >> 5;
    int lane = tid & 31;
    int g    = lane >> 2;
    int t    = lane & 3;
    int wm   = (w & 3) * 32;      // warp m offset in tile
    int wn   = (w >> 2) * 32;     // warp n offset in tile

    int lrow = tid >> 2;          // 0..63
    int lcol = (tid & 3) * 4;     // 0,4,8,12

    float c[2][4][4] = {};

    for (int k0 = 0; k0 < EE; k0 += TK) {
        __syncthreads();
        #pragma unroll
        for (int i = 0; i < 2; i++) {
            float4 v = *(const float4*)(A + (size_t)(m0 + lrow + i*64) * EE + k0 + lcol);
            As[lrow + i*64][lcol+0] = __uint_as_float(cvt_tf32(v.x));
            As[lrow + i*64][lcol+1] = __uint_as_float(cvt_tf32(v.y));
            As[lrow + i*64][lcol+2] = __uint_as_float(cvt_tf32(v.z));
            As[lrow + i*64][lcol+3] = __uint_as_float(cvt_tf32(v.w));
        }
        {
            float4 v = *(const float4*)(W + (size_t)(n0 + lrow) * EE + k0 + lcol);
            Bs[lrow][lcol+0] = __uint_as_float(cvt_tf32(v.x));
            Bs[lrow][lcol+1] = __uint_as_float(cvt_tf32(v.y));
            Bs[lrow][lcol+2] = __uint_as_float(cvt_tf32(v.z));
            Bs[lrow][lcol+3] = __uint_as_float(cvt_tf32(v.w));
        }
        __syncthreads();

        #pragma unroll
        for (int ks = 0; ks < 2; ks++) {
            int kk = ks * 8;
            unsigned a[2][4];
            #pragma unroll
            for (int mt = 0; mt < 2; mt++) {
                int r = wm + mt*16;
                a[mt][0] = __float_as_uint(As[r + g    ][kk + t    ]);
                a[mt][1] = __float_as_uint(As[r + g + 8][kk + t    ]);
                a[mt][2] = __float_as_uint(As[r + g    ][kk + t + 4]);
                a[mt][3] = __float_as_uint(As[r + g + 8][kk + t + 4]);
            }
            #pragma unroll
            for (int nt = 0; nt < 4; nt++) {
                unsigned b0 = __float_as_uint(Bs[wn + nt*8 + g][kk + t    ]);
                unsigned b1 = __float_as_uint(Bs[wn + nt*8 + g][kk + t + 4]);
                #pragma unroll
                for (int mt = 0; mt < 2; mt++)
                    mma_tf32(c[mt][nt][0], c[mt][nt][1], c[mt][nt][2], c[mt][nt][3],
                             a[mt][0], a[mt][1], a[mt][2], a[mt][3], b0, b1);
            }
        }
    }

    // epilogue: rows r = m0+wm+mt*16+g(+8), cols n = n0+wn+nt*8+2t (+1)
    #pragma unroll
    for (int mt = 0; mt < 2; mt++) {
        int rA = m0 + wm + mt*16 + g;
        int rB = rA + 8;
        #pragma unroll
        for (int nt = 0; nt < 4; nt++) {
            int n = n0 + wn + nt*8 + 2*t;
            epi(rA, n, c[mt][nt][0], c[mt][nt][1]);
            epi(rB, n, c[mt][nt][2], c[mt][nt][3]);
        }
    }
}

__global__ void __launch_bounds__(256) qkv_tc_kernel(
    const float* __restrict__ x,
    const float* __restrict__ W0, const float* __restrict__ b0,
    const float* __restrict__ W1, const float* __restrict__ b1,
    const float* __restrict__ W2, const float* __restrict__ b2)
{
    const float* W; const float* bias; float* out;
    int z = blockIdx.z;
    if (z == 0)      { W = W0; bias = b0; out = g_q; }
    else if (z == 1) { W = W1; bias = b1; out = g_k; }
    else             { W = W2; bias = b2; out = g_v; }

    int m0 = blockIdx.x * TM;
    int n0 = blockIdx.y * TN;

    QKVEpilogue epi;
    epi.out = out; epi.bias = bias;
    epi.b = m0 >> 11;             // TM=128 divides TT=2048: block in one batch
    epi.tb = m0 & (TT - 1);
    epi.m0 = m0;

    gemm_tf32_body(x, W, m0, n0, epi);
}

__global__ void __launch_bounds__(256) proj_tc_kernel(
    const float* __restrict__ Wo, const float* __restrict__ bo,
    float* __restrict__ out)
{
    int m0 = blockIdx.x * TM;
    int n0 = blockIdx.y * TN;

    ProjEpilogue epi;
    epi.out = out; epi.bias = bo;

    gemm_tf32_body(g_ctx, Wo, m0, n0, epi);
}

// ---------------------------------------------------------------------------
// Flash attention with mma.sync m16n8k8 tf32.
// Block = 4 warps, 64 queries (warp w owns rows qw..qw+15). 64-key tiles.
// ---------------------------------------------------------------------------
#define KSTRIDE 36
#define PSTRIDE 68

__global__ void __launch_bounds__(128) attn_kernel()
{
    __shared__ float Ks[64][KSTRIDE];
    __shared__ float Vs[64][KSTRIDE];
    __shared__ float Pb[4][16][PSTRIDE];

    int tid  = threadIdx.x;
    int w    = tid >> 5;
    int lane = tid & 31;
    int g    = lane >> 2;
    int t    = lane & 3;

    int h = blockIdx.y, b = blockIdx.z;
    int q0 = blockIdx.x * 64;
    int qw = q0 + w * 16;
    int r0 = qw + g;
    int r1 = qw + g + 8;

    const float* Q = g_q + (size_t)((b*HH + h)) * TT * DD;
    const float* K = g_k + (size_t)((b*HH + h)) * TT * DD;
    const float* V = g_v + (size_t)((b*HH + h)) * TT * DD;

    const float scale = 0.17677669529663687f;  // 1/sqrt(32)
    unsigned qa[4][4];
    #pragma unroll
    for (int kk = 0; kk < 4; kk++) {
        qa[kk][0] = cvt_tf32(Q[(size_t)r0 * DD + kk*8 + t]     * scale);
        qa[kk][1] = cvt_tf32(Q[(size_t)r1 * DD + kk*8 + t]     * scale);
        qa[kk][2] = cvt_tf32(Q[(size_t)r0 * DD + kk*8 + t + 4] * scale);
        qa[kk][3] = cvt_tf32(Q[(size_t)r1 * DD + kk*8 + t + 4] * scale);
    }

    float o[4][4] = {};
    float m0 = -1e30f, m1 = -1e30f, l0 = 0.f, l1 = 0.f;

    int ntiles = blockIdx.x + 1;

    int lrow = tid >> 1;
    int lcb  = (tid & 1) * 16;

    for (int tile = 0; tile < ntiles; tile++) {
        int j0 = tile * 64;
        __syncthreads();
        {
            const float* kp = K + (size_t)(j0 + lrow) * DD + lcb;
            const float* vp = V + (size_t)(j0 + lrow) * DD + lcb;
            #pragma unroll
            for (int i = 0; i < 4; i++) {
                float4 kv = *(const float4*)(kp + i*4);
                float4 vv = *(const float4*)(vp + i*4);
                float4 ko, vo;
                ko.x = __uint_as_float(cvt_tf32(kv.x));
                ko.y = __uint_as_float(cvt_tf32(kv.y));
                ko.z = __uint_as_float(cvt_tf32(kv.z));
                ko.w = __uint_as_float(cvt_tf32(kv.w));
                vo.x = __uint_as_float(cvt_tf32(vv.x));
                vo.y = __uint_as_float(cvt_tf32(vv.y));
                vo.z = __uint_as_float(cvt_tf32(vv.z));
                vo.w = __uint_as_float(cvt_tf32(vv.w));
                *(float4*)&Ks[lrow][lcb + i*4] = ko;
                *(float4*)&Vs[lrow][lcb + i*4] = vo;
            }
        }
        __syncthreads();

        if (j0 > qw + 15) continue;

        float sc[8][4];
        #pragma unroll
        for (int nt = 0; nt < 8; nt++) {
            float c0 = 0.f, c1 = 0.f, c2 = 0.f, c3 = 0.f;
            #pragma unroll
            for (int kk = 0; kk < 4; kk++) {
                unsigned b0 = __float_as_uint(Ks[nt*8 + g][kk*8 + t]);
                unsigned b1 = __float_as_uint(Ks[nt*8 + g][kk*8 + t + 4]);
                mma_tf32(c0, c1, c2, c3,
                         qa[kk][0], qa[kk][1], qa[kk][2], qa[kk][3], b0, b1);
            }
            sc[nt][0] = c0; sc[nt][1] = c1; sc[nt][2] = c2; sc[nt][3] = c3;
        }

        #pragma unroll
        for (int nt = 0; nt < 8; nt++) {
            int cA = j0 + nt*8 + 2*t;
            int cB = cA + 1;
            bool okA = (cA % JOINED) != (JOINED - 1);
            bool okB = (cB % JOINED) != (JOINED - 1);
            if (!(okA && cA <= r0)) sc[nt][0] = -1e30f;
            if (!(okB && cB <= r0)) sc[nt][1] = -1e30f;
            if (!(okA && cA <= r1)) sc[nt][2] = -1e30f;
            if (!(okB && cB <= r1)) sc[nt][3] = -1e30f;
        }

        float mx0 = -1e30f, mx1 = -1e30f;
        #pragma unroll
        for (int nt = 0; nt < 8; nt++) {
            mx0 = fmaxf(mx0, fmaxf(sc[nt][0], sc[nt][1]));
            mx1 = fmaxf(mx1, fmaxf(sc[nt][2], sc[nt][3]));
        }
        mx0 = fmaxf(mx0, __shfl_xor_sync(0xffffffffu, mx0, 1));
        mx0 = fmaxf(mx0, __shfl_xor_sync(0xffffffffu, mx0, 2));
        mx1 = fmaxf(mx1, __shfl_xor_sync(0xffffffffu, mx1, 1));
        mx1 = fmaxf(mx1, __shfl_xor_sync(0xffffffffu, mx1, 2));

        float mn0 = fmaxf(m0, mx0), mn1 = fmaxf(m1, mx1);
        float cr0 = __expf(m0 - mn0), cr1 = __expf(m1 - mn1);
        m0 = mn0; m1 = mn1;

        __syncwarp();

        float ls0 = 0.f, ls1 = 0.f;
        #pragma unroll
        for (int nt = 0; nt < 8; nt++) {
            float p0 = __expf(sc[nt][0] - mn0);
            float p1 = __expf(sc[nt][1] - mn0);
            float p2 = __expf(sc[nt][2] - mn1);
            float p3 = __expf(sc[nt][3] - mn1);
            ls0 += p0 + p1;
            ls1 += p2 + p3;
            Pb[w][g    ][nt*8 + 2*t    ] = __uint_as_float(cvt_tf32(p0));
            Pb[w][g    ][nt*8 + 2*t + 1] = __uint_as_float(cvt_tf32(p1));
            Pb[w][g + 8][nt*8 + 2*t    ] = __uint_as_float(cvt_tf32(p2));
            Pb[w][g + 8][nt*8 + 2*t + 1] = __uint_as_float(cvt_tf32(p3));
        }
        ls0 += __shfl_xor_sync(0xffffffffu, ls0, 1);
        ls0 += __shfl_xor_sync(0xffffffffu, ls0, 2);
        ls1 += __shfl_xor_sync(0xffffffffu, ls1, 1);
        ls1 += __shfl_xor_sync(0xffffffffu, ls1, 2);
        l0 = l0 * cr0 + ls0;
        l1 = l1 * cr1 + ls1;

        #pragma unroll
        for (int dn = 0; dn < 4; dn++) {
            o[dn][0] *= cr0; o[dn][1] *= cr0;
            o[dn][2] *= cr1; o[dn][3] *= cr1;
        }

        __syncwarp();

        #pragma unroll
        for (int kk = 0; kk < 8; kk++) {
            unsigned pa0 = __float_as_uint(Pb[w][g    ][kk*8 + t    ]);
            unsigned pa1 = __float_as_uint(Pb[w][g + 8][kk*8 + t    ]);
            unsigned pa2 = __float_as_uint(Pb[w][g    ][kk*8 + t + 4]);
            unsigned pa3 = __float_as_uint(Pb[w][g + 8][kk*8 + t + 4]);
            #pragma unroll
            for (int dn = 0; dn < 4; dn++) {
                unsigned b0 = __float_as_uint(Vs[kk*8 + t    ][dn*8 + g]);
                unsigned b1 = __float_as_uint(Vs[kk*8 + t + 4][dn*8 + g]);
                mma_tf32(o[dn][0], o[dn][1], o[dn][2], o[dn][3],
                         pa0, pa1, pa2, pa3, b0, b1);
            }
        }
    }

    float il0 = 1.f / l0, il1 = 1.f / l1;
    float* op0 = g_ctx + (size_t)(b*TT + r0) * EE + h*DD;
    float* op1 = g_ctx + (size_t)(b*TT + r1) * EE + h*DD;
    #pragma unroll
    for (int dn = 0; dn < 4; dn++) {
        float2 v0; v0.x = o[dn][0] * il0; v0.y = o[dn][1] * il0;
        float2 v1; v1.x = o[dn][2] * il1; v1.y = o[dn][3] * il1;
        *(float2*)(op0 + dn*8 + 2*t) = v0;
        *(float2*)(op1 + dn*8 + 2*t) = v1;
    }
}

// ---------------------------------------------------------------------------
extern "C" void kernel_launch(void* const* d_in, const int* in_sizes, int n_in,
                              void* d_out, int out_size)
{
    const float* x  = (const float*)d_in[0];
    const float* Wq = (const float*)d_in[1];
    const float* bq = (const float*)d_in[2];
    const float* Wk = (const float*)d_in[3];
    const float* bk = (const float*)d_in[4];
    const float* Wv = (const float*)d_in[5];
    const float* bv = (const float*)d_in[6];
    const float* Wo = (const float*)d_in[7];
    const float* bo = (const float*)d_in[8];
    float* out = (float*)d_out;

    dim3 gqkv((BB*TT)/TM, EE/TN, 3);
    qkv_tc_kernel<<<gqkv, 256>>>(x, Wq, bq, Wk, bk, Wv, bv);

    dim3 gattn(TT/64, HH, BB);
    attn_kernel<<<gattn, 128>>>();

    dim3 gproj((BB*TT)/TM, EE/TN, 1);
    proj_tc_kernel<<<gproj, 256>>>(Wo, bo, out);
}

// round 9
// speedup vs baseline: 3.8320x; 1.3860x over previous
#include <cuda_runtime.h>
#include <cuda_fp16.h>
#include <math.h>

#define BB 4
#define TT 2048
#define EE 256
#define HH 8
#define DD 32
#define JOINED 25

// Scratch (allocation-free rule: __device__ globals)
__device__ float g_q[BB*HH*TT*DD];
__device__ float g_k[BB*HH*TT*DD];
__device__ float g_v[BB*HH*TT*DD];
__device__ float g_ctx[BB*TT*EE];

__device__ __forceinline__ unsigned pk(float lo, float hi) {
    __half2 h = __floats2half2_rn(lo, hi);
    return *(unsigned*)&h;
}

__device__ __forceinline__ void mma_f16(
    float& c0, float& c1, float& c2, float& c3,
    unsigned a0, unsigned a1, unsigned a2, unsigned a3,
    unsigned b0, unsigned b1)
{
    asm volatile(
        "mma.sync.aligned.m16n8k16.row.col.f32.f16.f16.f32 "
        "{%0,%1,%2,%3}, {%4,%5,%6,%7}, {%8,%9}, {%0,%1,%2,%3};\n"
        : "+f"(c0), "+f"(c1), "+f"(c2), "+f"(c3)
        : "r"(a0), "r"(a1), "r"(a2), "r"(a3), "r"(b0), "r"(b1));
}

// ---------------------------------------------------------------------------
// Epilogue functors
// ---------------------------------------------------------------------------
struct QKVEpilogue {
    float* out;            // g_q / g_k / g_v, layout [B,H,T,D]
    const float* bias;
    int b, tb, m0;
    __device__ __forceinline__ void operator()(int r, int n, float v0, float v1) const {
        int trow = tb + (r - m0);
        int h = n >> 5, d = n & 31;
        float2 o;
        o.x = v0 + bias[n];
        o.y = v1 + bias[n + 1];
        *(float2*)(out + ((size_t)((b*HH + h) * TT + trow)) * DD + d) = o;
    }
};

struct ProjEpilogue {
    float* out;            // [B*T, E]
    const float* bias;
    __device__ __forceinline__ void operator()(int r, int n, float v0, float v1) const {
        float2 o;
        o.x = v0 + bias[n];
        o.y = v1 + bias[n + 1];
        *(float2*)(out + (size_t)r * EE + n) = o;
    }
};

// ---------------------------------------------------------------------------
// FP16 tensor-core GEMM: y[m][n] = sum_k A[m][k] * W[n][k] (+ bias in epi)
// Block tile 128x64, K-step 32, register-prefetch double buffering.
// smem: half rows, stride 40 halves (20 words): bank(g,t) = (20g+t) mod 32,
// all 32 distinct -> conflict-free fragment gathers.
// ---------------------------------------------------------------------------
#define TM 128
#define TN 64
#define TK 32
#define HS 40

template <typename EpiF>
__device__ __forceinline__ void gemm_f16_body(
    const float* __restrict__ A, const float* __restrict__ W,
    int m0, int n0, EpiF epi)
{
    __shared__ __half As[TM][HS];
    __shared__ __half Bs[TN][HS];

    int tid  = threadIdx.x;
    int w    = tid >> 5;
    int lane = tid & 31;
    int g    = lane >> 2;
    int t    = lane & 3;
    int wm   = (w & 3) * 32;
    int wn   = (w >> 2) * 32;

    int arow = tid >> 1;           // 0..127
    int acb  = (tid & 1) * 16;     // 0 or 16
    int brow = tid >> 2;           // 0..63
    int bcb  = (tid & 3) * 8;      // 0,8,16,24

    const float* Ap = A + (size_t)(m0 + arow) * EE + acb;
    const float* Bp = W + (size_t)(n0 + brow) * EE + bcb;

    float4 ar[4], br[2];
    #pragma unroll
    for (int i = 0; i < 4; i++) ar[i] = *(const float4*)(Ap + i*4);
    br[0] = *(const float4*)(Bp);
    br[1] = *(const float4*)(Bp + 4);

    float c[2][4][4] = {};

    for (int k0 = 0; k0 < EE; k0 += TK) {
        __syncthreads();
        {
            uint4 u;
            u.x = pk(ar[0].x, ar[0].y); u.y = pk(ar[0].z, ar[0].w);
            u.z = pk(ar[1].x, ar[1].y); u.w = pk(ar[1].z, ar[1].w);
            *(uint4*)&As[arow][acb] = u;
            u.x = pk(ar[2].x, ar[2].y); u.y = pk(ar[2].z, ar[2].w);
            u.z = pk(ar[3].x, ar[3].y); u.w = pk(ar[3].z, ar[3].w);
            *(uint4*)&As[arow][acb + 8] = u;
            u.x = pk(br[0].x, br[0].y); u.y = pk(br[0].z, br[0].w);
            u.z = pk(br[1].x, br[1].y); u.w = pk(br[1].z, br[1].w);
            *(uint4*)&Bs[brow][bcb] = u;
        }
        if (k0 + TK < EE) {
            #pragma unroll
            for (int i = 0; i < 4; i++) ar[i] = *(const float4*)(Ap + k0 + TK + i*4);
            br[0] = *(const float4*)(Bp + k0 + TK);
            br[1] = *(const float4*)(Bp + k0 + TK + 4);
        }
        __syncthreads();

        #pragma unroll
        for (int kk = 0; kk < 2; kk++) {
            int kc = kk * 16 + 2*t;
            unsigned a[2][4];
            #pragma unroll
            for (int mt = 0; mt < 2; mt++) {
                int r = wm + mt*16;
                a[mt][0] = *(unsigned*)&As[r + g    ][kc    ];
                a[mt][1] = *(unsigned*)&As[r + g + 8][kc    ];
                a[mt][2] = *(unsigned*)&As[r + g    ][kc + 8];
                a[mt][3] = *(unsigned*)&As[r + g + 8][kc + 8];
            }
            #pragma unroll
            for (int nt = 0; nt < 4; nt++) {
                unsigned b0 = *(unsigned*)&Bs[wn + nt*8 + g][kc    ];
                unsigned b1 = *(unsigned*)&Bs[wn + nt*8 + g][kc + 8];
                #pragma unroll
                for (int mt = 0; mt < 2; mt++)
                    mma_f16(c[mt][nt][0], c[mt][nt][1], c[mt][nt][2], c[mt][nt][3],
                            a[mt][0], a[mt][1], a[mt][2], a[mt][3], b0, b1);
            }
        }
    }

    #pragma unroll
    for (int mt = 0; mt < 2; mt++) {
        int rA = m0 + wm + mt*16 + g;
        int rB = rA + 8;
        #pragma unroll
        for (int nt = 0; nt < 4; nt++) {
            int n = n0 + wn + nt*8 + 2*t;
            epi(rA, n, c[mt][nt][0], c[mt][nt][1]);
            epi(rB, n, c[mt][nt][2], c[mt][nt][3]);
        }
    }
}

__global__ void __launch_bounds__(256) qkv_tc_kernel(
    const float* __restrict__ x,
    const float* __restrict__ W0, const float* __restrict__ b0,
    const float* __restrict__ W1, const float* __restrict__ b1,
    const float* __restrict__ W2, const float* __restrict__ b2)
{
    const float* W; const float* bias; float* out;
    int z = blockIdx.z;
    if (z == 0)      { W = W0; bias = b0; out = g_q; }
    else if (z == 1) { W = W1; bias = b1; out = g_k; }
    else             { W = W2; bias = b2; out = g_v; }

    int m0 = blockIdx.x * TM;
    int n0 = blockIdx.y * TN;

    QKVEpilogue epi;
    epi.out = out; epi.bias = bias;
    epi.b = m0 >> 11;
    epi.tb = m0 & (TT - 1);
    epi.m0 = m0;

    gemm_f16_body(x, W, m0, n0, epi);
}

__global__ void __launch_bounds__(256) proj_tc_kernel(
    const float* __restrict__ Wo, const float* __restrict__ bo,
    float* __restrict__ out)
{
    int m0 = blockIdx.x * TM;
    int n0 = blockIdx.y * TN;

    ProjEpilogue epi;
    epi.out = out; epi.bias = bo;

    gemm_f16_body(g_ctx, Wo, m0, n0, epi);
}

// ---------------------------------------------------------------------------
// Flash attention, fp16 m16n8k16 MMA.
// Block = 4 warps, 64 queries; 64-key tiles; register-prefetch pipelining.
// Ks [key][dim] stride 40 halves; Vt [dim][key] stride 72 halves
// (bank(g,t) = 4g+t mod 32, conflict-free B gathers).
// P fragments pack directly from softmax registers (S C-layout == PV A-layout).
// ---------------------------------------------------------------------------
#define AKS 40
#define AVS 72

__global__ void __launch_bounds__(128) attn_kernel()
{
    __shared__ __half Ks[64][AKS];
    __shared__ __half Vt[DD][AVS];

    int tid  = threadIdx.x;
    int w    = tid >> 5;
    int lane = tid & 31;
    int g    = lane >> 2;
    int t    = lane & 3;

    int h = blockIdx.y, b = blockIdx.z;
    int q0 = blockIdx.x * 64;
    int qw = q0 + w * 16;
    int r0 = qw + g;
    int r1 = r0 + 8;

    const float* Q = g_q + (size_t)(b*HH + h) * TT * DD;
    const float* K = g_k + (size_t)(b*HH + h) * TT * DD;
    const float* V = g_v + (size_t)(b*HH + h) * TT * DD;

    const float scale = 0.17677669529663687f;  // 1/sqrt(32)
    unsigned qa[2][4];
    #pragma unroll
    for (int kk = 0; kk < 2; kk++) {
        int kc = kk*16 + 2*t;
        float2 x0 = *(const float2*)(Q + (size_t)r0*DD + kc);
        float2 x1 = *(const float2*)(Q + (size_t)r1*DD + kc);
        float2 x2 = *(const float2*)(Q + (size_t)r0*DD + kc + 8);
        float2 x3 = *(const float2*)(Q + (size_t)r1*DD + kc + 8);
        qa[kk][0] = pk(x0.x*scale, x0.y*scale);
        qa[kk][1] = pk(x1.x*scale, x1.y*scale);
        qa[kk][2] = pk(x2.x*scale, x2.y*scale);
        qa[kk][3] = pk(x3.x*scale, x3.y*scale);
    }

    float o[4][4] = {};
    float m0 = -1e30f, m1 = -1e30f, l0 = 0.f, l1 = 0.f;

    int ntiles = blockIdx.x + 1;

    int lrow = tid >> 1;           // 0..63 (key)
    int lcb  = (tid & 1) * 16;     // dim half

    // prefetch tile 0
    float4 kr[4], vr[4];
    {
        const float* kp = K + (size_t)lrow * DD + lcb;
        const float* vp = V + (size_t)lrow * DD + lcb;
        #pragma unroll
        for (int i = 0; i < 4; i++) { kr[i] = *(const float4*)(kp + i*4); vr[i] = *(const float4*)(vp + i*4); }
    }

    for (int tile = 0; tile < ntiles; tile++) {
        int j0 = tile * 64;
        __syncthreads();
        {
            uint4 u;
            u.x = pk(kr[0].x, kr[0].y); u.y = pk(kr[0].z, kr[0].w);
            u.z = pk(kr[1].x, kr[1].y); u.w = pk(kr[1].z, kr[1].w);
            *(uint4*)&Ks[lrow][lcb] = u;
            u.x = pk(kr[2].x, kr[2].y); u.y = pk(kr[2].z, kr[2].w);
            u.z = pk(kr[3].x, kr[3].y); u.w = pk(kr[3].z, kr[3].w);
            *(uint4*)&Ks[lrow][lcb + 8] = u;
            // V transpose scatter
            float vv[16] = {vr[0].x,vr[0].y,vr[0].z,vr[0].w, vr[1].x,vr[1].y,vr[1].z,vr[1].w,
                            vr[2].x,vr[2].y,vr[2].z,vr[2].w, vr[3].x,vr[3].y,vr[3].z,vr[3].w};
            #pragma unroll
            for (int i = 0; i < 16; i++) Vt[lcb + i][lrow] = __float2half(vv[i]);
        }
        if (tile + 1 < ntiles) {
            const float* kp = K + (size_t)((tile+1)*64 + lrow) * DD + lcb;
            const float* vp = V + (size_t)((tile+1)*64 + lrow) * DD + lcb;
            #pragma unroll
            for (int i = 0; i < 4; i++) { kr[i] = *(const float4*)(kp + i*4); vr[i] = *(const float4*)(vp + i*4); }
        }
        __syncthreads();

        // S = Q K^T (16 x 64)
        float sc[8][4];
        #pragma unroll
        for (int nt = 0; nt < 8; nt++) {
            float c0 = 0.f, c1 = 0.f, c2 = 0.f, c3 = 0.f;
            #pragma unroll
            for (int kk = 0; kk < 2; kk++) {
                int kc = kk*16 + 2*t;
                unsigned b0 = *(unsigned*)&Ks[nt*8 + g][kc    ];
                unsigned b1 = *(unsigned*)&Ks[nt*8 + g][kc + 8];
                mma_f16(c0, c1, c2, c3,
                        qa[kk][0], qa[kk][1], qa[kk][2], qa[kk][3], b0, b1);
            }
            sc[nt][0] = c0; sc[nt][1] = c1; sc[nt][2] = c2; sc[nt][3] = c3;
        }

        // mask: causal + (col % 25 == 24) zeroed columns
        #pragma unroll
        for (int nt = 0; nt < 8; nt++) {
            int cA = j0 + nt*8 + 2*t;
            int cB = cA + 1;
            bool okA = (cA % JOINED) != (JOINED - 1);
            bool okB = (cB % JOINED) != (JOINED - 1);
            if (!(okA && cA <= r0)) sc[nt][0] = -1e30f;
            if (!(okB && cB <= r0)) sc[nt][1] = -1e30f;
            if (!(okA && cA <= r1)) sc[nt][2] = -1e30f;
            if (!(okB && cB <= r1)) sc[nt][3] = -1e30f;
        }

        float mx0 = -1e30f, mx1 = -1e30f;
        #pragma unroll
        for (int nt = 0; nt < 8; nt++) {
            mx0 = fmaxf(mx0, fmaxf(sc[nt][0], sc[nt][1]));
            mx1 = fmaxf(mx1, fmaxf(sc[nt][2], sc[nt][3]));
        }
        mx0 = fmaxf(mx0, __shfl_xor_sync(0xffffffffu, mx0, 1));
        mx0 = fmaxf(mx0, __shfl_xor_sync(0xffffffffu, mx0, 2));
        mx1 = fmaxf(mx1, __shfl_xor_sync(0xffffffffu, mx1, 1));
        mx1 = fmaxf(mx1, __shfl_xor_sync(0xffffffffu, mx1, 2));

        float mn0 = fmaxf(m0, mx0), mn1 = fmaxf(m1, mx1);
        float cr0 = __expf(m0 - mn0), cr1 = __expf(m1 - mn1);
        m0 = mn0; m1 = mn1;

        unsigned pA[8], pB[8];
        float ls0 = 0.f, ls1 = 0.f;
        #pragma unroll
        for (int nt = 0; nt < 8; nt++) {
            float p0 = __expf(sc[nt][0] - mn0);
            float p1 = __expf(sc[nt][1] - mn0);
            float p2 = __expf(sc[nt][2] - mn1);
            float p3 = __expf(sc[nt][3] - mn1);
            ls0 += p0 + p1;
            ls1 += p2 + p3;
            pA[nt] = pk(p0, p1);
            pB[nt] = pk(p2, p3);
        }
        ls0 += __shfl_xor_sync(0xffffffffu, ls0, 1);
        ls0 += __shfl_xor_sync(0xffffffffu, ls0, 2);
        ls1 += __shfl_xor_sync(0xffffffffu, ls1, 1);
        ls1 += __shfl_xor_sync(0xffffffffu, ls1, 2);
        l0 = l0 * cr0 + ls0;
        l1 = l1 * cr1 + ls1;

        #pragma unroll
        for (int dn = 0; dn < 4; dn++) {
            o[dn][0] *= cr0; o[dn][1] *= cr0;
            o[dn][2] *= cr1; o[dn][3] *= cr1;
        }

        // O += P V  (P A-fragments come straight from pA/pB registers)
        #pragma unroll
        for (int kk = 0; kk < 4; kk++) {
            unsigned a0 = pA[2*kk], a1 = pB[2*kk], a2 = pA[2*kk+1], a3 = pB[2*kk+1];
            int kc = kk*16 + 2*t;
            #pragma unroll
            for (int dn = 0; dn < 4; dn++) {
                unsigned b0 = *(unsigned*)&Vt[dn*8 + g][kc    ];
                unsigned b1 = *(unsigned*)&Vt[dn*8 + g][kc + 8];
                mma_f16(o[dn][0], o[dn][1], o[dn][2], o[dn][3],
                        a0, a1, a2, a3, b0, b1);
            }
        }
    }

    float il0 = 1.f / l0, il1 = 1.f / l1;
    float* op0 = g_ctx + (size_t)(b*TT + r0) * EE + h*DD;
    float* op1 = g_ctx + (size_t)(b*TT + r1) * EE + h*DD;
    #pragma unroll
    for (int dn = 0; dn < 4; dn++) {
        float2 v0; v0.x = o[dn][0] * il0; v0.y = o[dn][1] * il0;
        float2 v1; v1.x = o[dn][2] * il1; v1.y = o[dn][3] * il1;
        *(float2*)(op0 + dn*8 + 2*t) = v0;
        *(float2*)(op1 + dn*8 + 2*t) = v1;
    }
}

// ---------------------------------------------------------------------------
extern "C" void kernel_launch(void* const* d_in, const int* in_sizes, int n_in,
                              void* d_out, int out_size)
{
    const float* x  = (const float*)d_in[0];
    const float* Wq = (const float*)d_in[1];
    const float* bq = (const float*)d_in[2];
    const float* Wk = (const float*)d_in[3];
    const float* bk = (const float*)d_in[4];
    const float* Wv = (const float*)d_in[5];
    const float* bv = (const float*)d_in[6];
    const float* Wo = (const float*)d_in[7];
    const float* bo = (const float*)d_in[8];
    float* out = (float*)d_out;

    dim3 gqkv((BB*TT)/TM, EE/TN, 3);
    qkv_tc_kernel<<<gqkv, 256>>>(x, Wq, bq, Wk, bk, Wv, bv);

    dim3 gattn(TT/64, HH, BB);
    attn_kernel<<<gattn, 128>>>();

    dim3 gproj((BB*TT)/TM, EE/TN, 1);
    proj_tc_kernel<<<gproj, 256>>>(Wo, bo, out);
}

// round 10
// speedup vs baseline: 4.4258x; 1.1550x over previous
#include <cuda_runtime.h>
#include <cuda_fp16.h>
#include <math.h>

#define BB 4
#define TT 2048
#define EE 256
#define HH 8
#define DD 32
#define JOINED 25

// Scratch (allocation-free rule: __device__ globals)
__device__ __half g_qh[BB*HH*TT*DD];            // [B,H,T,D]
__device__ __half g_kh[BB*HH*TT*DD];            // [B,H,T,D]
__device__ __half g_vt[BB*HH*TT*DD];            // [B,H,D,T]  (pre-transposed)
__device__ float  g_ctx[BB*TT*EE];

__device__ __forceinline__ unsigned pk(float lo, float hi) {
    __half2 h = __floats2half2_rn(lo, hi);
    return *(unsigned*)&h;
}

__device__ __forceinline__ float ex2(float x) {
    float y;
    asm("ex2.approx.f32 %0, %1;" : "=f"(y) : "f"(x));
    return y;
}

__device__ __forceinline__ void mma_f16(
    float& c0, float& c1, float& c2, float& c3,
    unsigned a0, unsigned a1, unsigned a2, unsigned a3,
    unsigned b0, unsigned b1)
{
    asm volatile(
        "mma.sync.aligned.m16n8k16.row.col.f32.f16.f16.f32 "
        "{%0,%1,%2,%3}, {%4,%5,%6,%7}, {%8,%9}, {%0,%1,%2,%3};\n"
        : "+f"(c0), "+f"(c1), "+f"(c2), "+f"(c3)
        : "r"(a0), "r"(a1), "r"(a2), "r"(a3), "r"(b0), "r"(b1));
}

// ---------------------------------------------------------------------------
// Epilogue functors
// ---------------------------------------------------------------------------
struct QKEpilogue {              // half out, [B,H,T,D]
    __half* out;
    const float* bias;
    int b, tb, m0;
    __device__ __forceinline__ void operator()(int r, int n, float v0, float v1) const {
        int trow = tb + (r - m0);
        int h = n >> 5, d = n & 31;
        __half2 hv = __floats2half2_rn(v0 + bias[n], v1 + bias[n + 1]);
        *(__half2*)(out + ((size_t)((b*HH + h) * TT + trow)) * DD + d) = hv;
    }
};

struct VTEpilogue {              // half out, transposed [B,H,D,T]
    __half* out;
    const float* bias;
    int b, tb, m0;
    __device__ __forceinline__ void operator()(int r, int n, float v0, float v1) const {
        int trow = tb + (r - m0);
        int h = n >> 5, d = n & 31;
        size_t base = (size_t)(b*HH + h) * DD;
        out[(base + d    ) * TT + trow] = __float2half(v0 + bias[n]);
        out[(base + d + 1) * TT + trow] = __float2half(v1 + bias[n + 1]);
    }
};

struct ProjEpilogue {            // fp32 out, [B*T, E]
    float* out;
    const float* bias;
    __device__ __forceinline__ void operator()(int r, int n, float v0, float v1) const {
        float2 o;
        o.x = v0 + bias[n];
        o.y = v1 + bias[n + 1];
        *(float2*)(out + (size_t)r * EE + n) = o;
    }
};

// ---------------------------------------------------------------------------
// FP16 tensor-core GEMM: y[m][n] = sum_k A[m][k] * W[n][k] (+ bias in epi)
// Block tile 128x64, K-step 64 (4 steps, 4 sync pairs), register prefetch.
// smem half rows, stride 72 halves (36 words): bank(g,t)=(36g+t)%32=4g+t,
// all distinct -> conflict-free fragment gathers.
// ---------------------------------------------------------------------------
#define TM 128
#define TN 64
#define TK 64
#define HS 72

template <typename EpiF>
__device__ __forceinline__ void gemm_f16_body(
    const float* __restrict__ A, const float* __restrict__ W,
    int m0, int n0, EpiF epi)
{
    __shared__ __half As[TM][HS];
    __shared__ __half Bs[TN][HS];

    int tid  = threadIdx.x;
    int w    = tid >> 5;
    int lane = tid & 31;
    int g    = lane >> 2;
    int t    = lane & 3;
    int wm   = (w & 3) * 32;
    int wn   = (w >> 2) * 32;

    int arow = tid >> 1;           // 0..127
    int acb  = (tid & 1) * 32;     // half-col base: 0 or 32
    int brow = tid >> 2;           // 0..63
    int bcb  = (tid & 3) * 16;     // 0,16,32,48

    const float* Ap = A + (size_t)(m0 + arow) * EE + acb;
    const float* Bp = W + (size_t)(n0 + brow) * EE + bcb;

    float4 ar[8], br[4];
    #pragma unroll
    for (int i = 0; i < 8; i++) ar[i] = *(const float4*)(Ap + i*4);
    #pragma unroll
    for (int i = 0; i < 4; i++) br[i] = *(const float4*)(Bp + i*4);

    float c[2][4][4] = {};

    for (int k0 = 0; k0 < EE; k0 += TK) {
        __syncthreads();
        #pragma unroll
        for (int i = 0; i < 4; i++) {
            uint4 u;
            u.x = pk(ar[2*i].x, ar[2*i].y);     u.y = pk(ar[2*i].z, ar[2*i].w);
            u.z = pk(ar[2*i+1].x, ar[2*i+1].y); u.w = pk(ar[2*i+1].z, ar[2*i+1].w);
            *(uint4*)&As[arow][acb + i*8] = u;
        }
        #pragma unroll
        for (int i = 0; i < 2; i++) {
            uint4 u;
            u.x = pk(br[2*i].x, br[2*i].y);     u.y = pk(br[2*i].z, br[2*i].w);
            u.z = pk(br[2*i+1].x, br[2*i+1].y); u.w = pk(br[2*i+1].z, br[2*i+1].w);
            *(uint4*)&Bs[brow][bcb + i*8] = u;
        }
        if (k0 + TK < EE) {
            #pragma unroll
            for (int i = 0; i < 8; i++) ar[i] = *(const float4*)(Ap + k0 + TK + i*4);
            #pragma unroll
            for (int i = 0; i < 4; i++) br[i] = *(const float4*)(Bp + k0 + TK + i*4);
        }
        __syncthreads();

        #pragma unroll
        for (int kk = 0; kk < 4; kk++) {
            int kc = kk * 16 + 2*t;
            unsigned a[2][4];
            #pragma unroll
            for (int mt = 0; mt < 2; mt++) {
                int r = wm + mt*16;
                a[mt][0] = *(unsigned*)&As[r + g    ][kc    ];
                a[mt][1] = *(unsigned*)&As[r + g + 8][kc    ];
                a[mt][2] = *(unsigned*)&As[r + g    ][kc + 8];
                a[mt][3] = *(unsigned*)&As[r + g + 8][kc + 8];
            }
            #pragma unroll
            for (int nt = 0; nt < 4; nt++) {
                unsigned b0 = *(unsigned*)&Bs[wn + nt*8 + g][kc    ];
                unsigned b1 = *(unsigned*)&Bs[wn + nt*8 + g][kc + 8];
                #pragma unroll
                for (int mt = 0; mt < 2; mt++)
                    mma_f16(c[mt][nt][0], c[mt][nt][1], c[mt][nt][2], c[mt][nt][3],
                            a[mt][0], a[mt][1], a[mt][2], a[mt][3], b0, b1);
            }
        }
    }

    #pragma unroll
    for (int mt = 0; mt < 2; mt++) {
        int rA = m0 + wm + mt*16 + g;
        int rB = rA + 8;
        #pragma unroll
        for (int nt = 0; nt < 4; nt++) {
            int n = n0 + wn + nt*8 + 2*t;
            epi(rA, n, c[mt][nt][0], c[mt][nt][1]);
            epi(rB, n, c[mt][nt][2], c[mt][nt][3]);
        }
    }
}

__global__ void __launch_bounds__(256, 2) qkv_tc_kernel(
    const float* __restrict__ x,
    const float* __restrict__ W0, const float* __restrict__ b0,
    const float* __restrict__ W1, const float* __restrict__ b1,
    const float* __restrict__ W2, const float* __restrict__ b2)
{
    int m0 = blockIdx.x * TM;
    int n0 = blockIdx.y * TN;
    int z  = blockIdx.z;

    if (z == 2) {
        VTEpilogue epi;
        epi.out = g_vt; epi.bias = b2;
        epi.b = m0 >> 11; epi.tb = m0 & (TT - 1); epi.m0 = m0;
        gemm_f16_body(x, W2, m0, n0, epi);
    } else {
        QKEpilogue epi;
        epi.out  = (z == 0) ? g_qh : g_kh;
        epi.bias = (z == 0) ? b0 : b1;
        epi.b = m0 >> 11; epi.tb = m0 & (TT - 1); epi.m0 = m0;
        gemm_f16_body(x, (z == 0) ? W0 : W1, m0, n0, epi);
    }
}

__global__ void __launch_bounds__(256, 2) proj_tc_kernel(
    const float* __restrict__ Wo, const float* __restrict__ bo,
    float* __restrict__ out)
{
    int m0 = blockIdx.x * TM;
    int n0 = blockIdx.y * TN;

    ProjEpilogue epi;
    epi.out = out; epi.bias = bo;

    gemm_f16_body(g_ctx, Wo, m0, n0, epi);
}

// ---------------------------------------------------------------------------
// Flash attention, fp16 m16n8k16 MMA, exp2-domain softmax.
// Block = 4 warps, 64 queries; 64-key tiles; register-prefetch pipelining.
// K/V arrive in half (V pre-transposed) -> staging is pure uint4 copies.
// Ks [key][dim] stride 40 halves; Vts [dim][key] stride 72 halves.
// ---------------------------------------------------------------------------
#define AKS 40
#define AVS 72

__global__ void __launch_bounds__(128) attn_kernel()
{
    __shared__ __half Ks[64][AKS];
    __shared__ __half Vts[DD][AVS];

    int tid  = threadIdx.x;
    int w    = tid >> 5;
    int lane = tid & 31;
    int g    = lane >> 2;
    int t    = lane & 3;

    int h = blockIdx.y, b = blockIdx.z;
    int q0 = blockIdx.x * 64;
    int qw = q0 + w * 16;
    int r0 = qw + g;
    int r1 = r0 + 8;

    const __half* Q  = g_qh + (size_t)(b*HH + h) * TT * DD;
    const __half* K  = g_kh + (size_t)(b*HH + h) * TT * DD;
    const __half* Vt = g_vt + (size_t)(b*HH + h) * DD * TT;

    // scale = 1/sqrt(32) * log2(e): softmax runs in exp2 domain
    const float scale = 0.17677669529663687f * 1.4426950408889634f;
    unsigned qa[2][4];
    #pragma unroll
    for (int kk = 0; kk < 2; kk++) {
        int kc = kk*16 + 2*t;
        #pragma unroll
        for (int f = 0; f < 4; f++) {
            int row = (f & 1) ? r1 : r0;
            int col = kc + ((f >> 1) ? 8 : 0);
            __half2 hv = *(const __half2*)(Q + (size_t)row*DD + col);
            float2 fv = __half22float2(hv);
            qa[kk][f] = pk(fv.x * scale, fv.y * scale);
        }
    }

    float o[4][4] = {};
    float m0 = -1e30f, m1 = -1e30f, l0 = 0.f, l1 = 0.f;

    int ntiles = blockIdx.x + 1;

    int lrow = tid >> 1;           // K loader: key row 0..63
    int lkc  = (tid & 1) * 16;     // half-col base 0/16
    int vrow = tid >> 2;           // V loader: dim row 0..31
    int vcb  = (tid & 3) * 16;     // key-col base 0,16,32,48

    uint4 kA, kB, vA, vB;
    {
        const __half* kp = K + (size_t)lrow * DD + lkc;
        const __half* vp = Vt + (size_t)vrow * TT + vcb;
        kA = *(const uint4*)(kp);
        kB = *(const uint4*)(kp + 8);
        vA = *(const uint4*)(vp);
        vB = *(const uint4*)(vp + 8);
    }

    for (int tile = 0; tile < ntiles; tile++) {
        int j0 = tile * 64;
        __syncthreads();
        *(uint4*)&Ks[lrow][lkc]      = kA;
        *(uint4*)&Ks[lrow][lkc + 8]  = kB;
        *(uint4*)&Vts[vrow][vcb]     = vA;
        *(uint4*)&Vts[vrow][vcb + 8] = vB;
        if (tile + 1 < ntiles) {
            const __half* kp = K + (size_t)(j0 + 64 + lrow) * DD + lkc;
            const __half* vp = Vt + (size_t)vrow * TT + j0 + 64 + vcb;
            kA = *(const uint4*)(kp);
            kB = *(const uint4*)(kp + 8);
            vA = *(const uint4*)(vp);
            vB = *(const uint4*)(vp + 8);
        }
        __syncthreads();

        if (j0 > qw + 15) continue;

        // S = Q K^T (16 x 64), scores already in log2 domain
        float sc[8][4];
        #pragma unroll
        for (int nt = 0; nt < 8; nt++) {
            float c0 = 0.f, c1 = 0.f, c2 = 0.f, c3 = 0.f;
            #pragma unroll
            for (int kk = 0; kk < 2; kk++) {
                int kc = kk*16 + 2*t;
                unsigned b0 = *(unsigned*)&Ks[nt*8 + g][kc    ];
                unsigned b1 = *(unsigned*)&Ks[nt*8 + g][kc + 8];
                mma_f16(c0, c1, c2, c3,
                        qa[kk][0], qa[kk][1], qa[kk][2], qa[kk][3], b0, b1);
            }
            sc[nt][0] = c0; sc[nt][1] = c1; sc[nt][2] = c2; sc[nt][3] = c3;
        }

        // mask: causal + (col % 25 == 24) zeroed columns
        #pragma unroll
        for (int nt = 0; nt < 8; nt++) {
            int cA = j0 + nt*8 + 2*t;
            int cB = cA + 1;
            bool okA = (cA % JOINED) != (JOINED - 1);
            bool okB = (cB % JOINED) != (JOINED - 1);
            if (!(okA && cA <= r0)) sc[nt][0] = -1e30f;
            if (!(okB && cB <= r0)) sc[nt][1] = -1e30f;
            if (!(okA && cA <= r1)) sc[nt][2] = -1e30f;
            if (!(okB && cB <= r1)) sc[nt][3] = -1e30f;
        }

        float mx0 = -1e30f, mx1 = -1e30f;
        #pragma unroll
        for (int nt = 0; nt < 8; nt++) {
            mx0 = fmaxf(mx0, fmaxf(sc[nt][0], sc[nt][1]));
            mx1 = fmaxf(mx1, fmaxf(sc[nt][2], sc[nt][3]));
        }
        mx0 = fmaxf(mx0, __shfl_xor_sync(0xffffffffu, mx0, 1));
        mx0 = fmaxf(mx0, __shfl_xor_sync(0xffffffffu, mx0, 2));
        mx1 = fmaxf(mx1, __shfl_xor_sync(0xffffffffu, mx1, 1));
        mx1 = fmaxf(mx1, __shfl_xor_sync(0xffffffffu, mx1, 2));

        float mn0 = fmaxf(m0, mx0), mn1 = fmaxf(m1, mx1);
        float cr0 = ex2(m0 - mn0), cr1 = ex2(m1 - mn1);
        m0 = mn0; m1 = mn1;

        unsigned pA[8], pB[8];
        float ls0 = 0.f, ls1 = 0.f;
        #pragma unroll
        for (int nt = 0; nt < 8; nt++) {
            float p0 = ex2(sc[nt][0] - mn0);
            float p1 = ex2(sc[nt][1] - mn0);
            float p2 = ex2(sc[nt][2] - mn1);
            float p3 = ex2(sc[nt][3] - mn1);
            ls0 += p0 + p1;
            ls1 += p2 + p3;
            pA[nt] = pk(p0, p1);
            pB[nt] = pk(p2, p3);
        }
        ls0 += __shfl_xor_sync(0xffffffffu, ls0, 1);
        ls0 += __shfl_xor_sync(0xffffffffu, ls0, 2);
        ls1 += __shfl_xor_sync(0xffffffffu, ls1, 1);
        ls1 += __shfl_xor_sync(0xffffffffu, ls1, 2);
        l0 = l0 * cr0 + ls0;
        l1 = l1 * cr1 + ls1;

        #pragma unroll
        for (int dn = 0; dn < 4; dn++) {
            o[dn][0] *= cr0; o[dn][1] *= cr0;
            o[dn][2] *= cr1; o[dn][3] *= cr1;
        }

        // O += P V  (P A-fragments straight from registers)
        #pragma unroll
        for (int kk = 0; kk < 4; kk++) {
            unsigned a0 = pA[2*kk], a1 = pB[2*kk], a2 = pA[2*kk+1], a3 = pB[2*kk+1];
            int kc = kk*16 + 2*t;
            #pragma unroll
            for (int dn = 0; dn < 4; dn++) {
                unsigned b0 = *(unsigned*)&Vts[dn*8 + g][kc    ];
                unsigned b1 = *(unsigned*)&Vts[dn*8 + g][kc + 8];
                mma_f16(o[dn][0], o[dn][1], o[dn][2], o[dn][3],
                        a0, a1, a2, a3, b0, b1);
            }
        }
    }

    float il0 = 1.f / l0, il1 = 1.f / l1;
    float* op0 = g_ctx + (size_t)(b*TT + r0) * EE + h*DD;
    float* op1 = g_ctx + (size_t)(b*TT + r1) * EE + h*DD;
    #pragma unroll
    for (int dn = 0; dn < 4; dn++) {
        float2 v0; v0.x = o[dn][0] * il0; v0.y = o[dn][1] * il0;
        float2 v1; v1.x = o[dn][2] * il1; v1.y = o[dn][3] * il1;
        *(float2*)(op0 + dn*8 + 2*t) = v0;
        *(float2*)(op1 + dn*8 + 2*t) = v1;
    }
}

// ---------------------------------------------------------------------------
extern "C" void kernel_launch(void* const* d_in, const int* in_sizes, int n_in,
                              void* d_out, int out_size)
{
    const float* x  = (const float*)d_in[0];
    const float* Wq = (const float*)d_in[1];
    const float* bq = (const float*)d_in[2];
    const float* Wk = (const float*)d_in[3];
    const float* bk = (const float*)d_in[4];
    const float* Wv = (const float*)d_in[5];
    const float* bv = (const float*)d_in[6];
    const float* Wo = (const float*)d_in[7];
    const float* bo = (const float*)d_in[8];
    float* out = (float*)d_out;

    dim3 gqkv((BB*TT)/TM, EE/TN, 3);
    qkv_tc_kernel<<<gqkv, 256>>>(x, Wq, bq, Wk, bk, Wv, bv);

    dim3 gattn(TT/64, HH, BB);
    attn_kernel<<<gattn, 128>>>();

    dim3 gproj((BB*TT)/TM, EE/TN, 1);
    proj_tc_kernel<<<gproj, 256>>>(Wo, bo, out);
}